// round 2
// baseline (speedup 1.0000x reference)
#include <cuda_runtime.h>
#include <math.h>

#define NN 50000
#define NE 800000
#define IND 256
#define DOUT 128
#define FDIM 256   // 2 heads * 128

// ---------------- scratch (static __device__, no allocation) ----------------
__device__ float g_Wh[NN * FDIM];   // 51.2 MB - fits L2
__device__ float g_s[NN * 2];
__device__ float g_t[NN * 2];
__device__ int   g_deg[NN];
__device__ int   g_off[NN + 1];
__device__ int   g_cur[NN];
__device__ int   g_dst[NE];

// ---------------- CSR build ----------------
__global__ void k_zero() {
    int i = blockIdx.x * blockDim.x + threadIdx.x;
    if (i < NN) g_deg[i] = 0;
}

// edge_index is int32 (JAX default x64-disabled downcasts int64 -> int32)
__global__ void k_count(const int* __restrict__ ei) {
    int e = blockIdx.x * blockDim.x + threadIdx.x;
    if (e < NE) {
        unsigned s = (unsigned)ei[e];
        if (s < NN) atomicAdd(&g_deg[s], 1);
    }
}

// single-block exclusive scan over 50000 ints (Hillis-Steele per 1024 chunk)
__global__ void k_scan() {
    __shared__ int sm[1024];
    __shared__ int carry_s;
    int tid = threadIdx.x;
    if (tid == 0) carry_s = 0;
    __syncthreads();
    for (int base = 0; base < NN; base += 1024) {
        int i = base + tid;
        int v = (i < NN) ? g_deg[i] : 0;
        sm[tid] = v;
        __syncthreads();
        for (int off = 1; off < 1024; off <<= 1) {
            int tv = (tid >= off) ? sm[tid - off] : 0;
            __syncthreads();
            sm[tid] += tv;
            __syncthreads();
        }
        int c = carry_s;
        if (i < NN) {
            int ex = c + sm[tid] - v;
            g_off[i] = ex;
            g_cur[i] = ex;
        }
        __syncthreads();
        if (tid == 0) carry_s = c + sm[1023];
        __syncthreads();
    }
    if (tid == 0) g_off[NN] = carry_s;
}

__global__ void k_scatter(const int* __restrict__ ei) {
    int e = blockIdx.x * blockDim.x + threadIdx.x;
    if (e < NE) {
        unsigned s = (unsigned)ei[e];
        unsigned d = (unsigned)ei[NE + e];
        if (s < NN && d < NN) {
            int p = atomicAdd(&g_cur[s], 1);
            if (p >= 0 && p < NE) g_dst[p] = (int)d;
        }
    }
}

// ---------------- GEMM: Wh = x @ W + b, fused s/t epilogue ----------------
// BM=64, BN=128 (one head per blockIdx.y), BK=32, 256 threads, f32x2 packed FMA.
__global__ __launch_bounds__(256) void k_gemm(const float* __restrict__ x,
                                              const float* __restrict__ W,
                                              const float* __restrict__ b,
                                              const float* __restrict__ a) {
    __shared__ float xs[32][65];   // xs[k][row], padded
    __shared__ float ws[32][128];  // ws[k][n]

    int tid  = threadIdx.x;
    int h    = blockIdx.y;                 // head / 128-col tile
    int row0 = blockIdx.x * 64;
    int tr   = tid >> 5;                   // warp id: rows tr*8 .. tr*8+7
    int tc   = tid & 31;                   // cols tc*4 .. tc*4+3 (within head)

    unsigned long long acc2[8][2];
    unsigned long long zz;
    asm("mov.b64 %0, {%1, %1};" : "=l"(zz) : "r"(0u));
#pragma unroll
    for (int i = 0; i < 8; i++) { acc2[i][0] = zz; acc2[i][1] = zz; }

    for (int k0 = 0; k0 < IND; k0 += 32) {
        // load x tile (64 rows x 32 k), transposed into xs[k][row]
#pragma unroll
        for (int q = 0; q < 2; q++) {
            int idx  = tid * 2 + q;
            int r    = idx >> 3;
            int kq   = (idx & 7) << 2;
            int grow = row0 + r;
            float4 xv = make_float4(0.f, 0.f, 0.f, 0.f);
            if (grow < NN) xv = *(const float4*)&x[grow * IND + k0 + kq];
            xs[kq + 0][r] = xv.x;
            xs[kq + 1][r] = xv.y;
            xs[kq + 2][r] = xv.z;
            xs[kq + 3][r] = xv.w;
        }
        // load W tile (32 k x 128 n)
        {
            int kr = tid >> 5;
            int nq = (tid & 31) << 2;
#pragma unroll
            for (int p = 0; p < 4; p++) {
                int k = kr + p * 8;
                *(float4*)&ws[k][nq] = *(const float4*)&W[(k0 + k) * FDIM + h * 128 + nq];
            }
        }
        __syncthreads();
#pragma unroll
        for (int kk = 0; kk < 32; kk++) {
            unsigned long long rn01 = *(const unsigned long long*)&ws[kk][tc * 4];
            unsigned long long rn23 = *(const unsigned long long*)&ws[kk][tc * 4 + 2];
#pragma unroll
            for (int i = 0; i < 8; i++) {
                float rm = xs[kk][tr * 8 + i];
                unsigned long long am;
                asm("mov.b64 %0, {%1, %1};" : "=l"(am) : "r"(__float_as_uint(rm)));
                asm("fma.rn.f32x2 %0, %1, %2, %3;"
                    : "=l"(acc2[i][0]) : "l"(am), "l"(rn01), "l"(acc2[i][0]));
                asm("fma.rn.f32x2 %0, %1, %2, %3;"
                    : "=l"(acc2[i][1]) : "l"(am), "l"(rn23), "l"(acc2[i][1]));
            }
        }
        __syncthreads();
    }

    // epilogue: bias, store Wh, fused s/t dot + warp reduce
    float4 bb = *(const float4*)&b[h * 128 + tc * 4];
    float as0 = a[tc * 4 + 0], as1 = a[tc * 4 + 1], as2 = a[tc * 4 + 2], as3 = a[tc * 4 + 3];
    float at0 = a[128 + tc * 4 + 0], at1 = a[128 + tc * 4 + 1];
    float at2 = a[128 + tc * 4 + 2], at3 = a[128 + tc * 4 + 3];

#pragma unroll
    for (int i = 0; i < 8; i++) {
        int grow = row0 + tr * 8 + i;
        unsigned int u0, u1, u2, u3;
        asm("mov.b64 {%0, %1}, %2;" : "=r"(u0), "=r"(u1) : "l"(acc2[i][0]));
        asm("mov.b64 {%0, %1}, %2;" : "=r"(u2), "=r"(u3) : "l"(acc2[i][1]));
        float f0 = __uint_as_float(u0) + bb.x;
        float f1 = __uint_as_float(u1) + bb.y;
        float f2 = __uint_as_float(u2) + bb.z;
        float f3 = __uint_as_float(u3) + bb.w;
        float ps = f0 * as0 + f1 * as1 + f2 * as2 + f3 * as3;
        float pt = f0 * at0 + f1 * at1 + f2 * at2 + f3 * at3;
#pragma unroll
        for (int off = 16; off > 0; off >>= 1) {
            ps += __shfl_down_sync(0xffffffffu, ps, off);
            pt += __shfl_down_sync(0xffffffffu, pt, off);
        }
        if (grow < NN) {
            *(float4*)&g_Wh[grow * FDIM + h * 128 + tc * 4] = make_float4(f0, f1, f2, f3);
            if (tc == 0) {
                g_s[grow * 2 + h] = ps;
                g_t[grow * 2 + h] = pt;
            }
        }
    }
}

// ---------------- per-node online softmax + aggregation (1 warp / node) ----
__global__ __launch_bounds__(256) void k_agg(float* __restrict__ out) {
    int gwarp = (blockIdx.x * blockDim.x + threadIdx.x) >> 5;
    int lane  = threadIdx.x & 31;
    if (gwarp >= NN) return;
    int n = gwarp;
    int start = g_off[n];
    int end   = g_off[n + 1];

    const float4* wh4  = (const float4*)g_Wh;
    float4*       out4 = (float4*)out;

    if (end == start) {  // deg == 0 -> h' = Wh
        out4[n * 64 + lane]      = wh4[n * 64 + lane];
        out4[n * 64 + 32 + lane] = wh4[n * 64 + 32 + lane];
        return;
    }

    float2 ss = *(const float2*)&g_s[n * 2];
    float m0 = -INFINITY, m1 = -INFINITY;
    float d0 = 0.f, d1 = 0.f;
    float4 a0 = make_float4(0.f, 0.f, 0.f, 0.f);
    float4 a1 = make_float4(0.f, 0.f, 0.f, 0.f);

    int dnext = g_dst[start];
    for (int i = start; i < end; i++) {
        int dd = dnext;
        if (i + 1 < end) dnext = g_dst[i + 1];

        float2 tt = *(const float2*)&g_t[dd * 2];
        float e0 = ss.x + tt.x; e0 = (e0 > 0.f) ? e0 : 0.2f * e0;
        float e1 = ss.y + tt.y; e1 = (e1 > 0.f) ? e1 : 0.2f * e1;

        float nm0 = fmaxf(m0, e0), nm1 = fmaxf(m1, e1);
        float c0 = __expf(m0 - nm0), c1 = __expf(m1 - nm1);
        float w0 = __expf(e0 - nm0), w1 = __expf(e1 - nm1);
        d0 = d0 * c0 + w0;  m0 = nm0;
        d1 = d1 * c1 + w1;  m1 = nm1;

        float4 v0 = wh4[dd * 64 + lane];
        float4 v1 = wh4[dd * 64 + 32 + lane];
        a0.x = a0.x * c0 + w0 * v0.x;  a0.y = a0.y * c0 + w0 * v0.y;
        a0.z = a0.z * c0 + w0 * v0.z;  a0.w = a0.w * c0 + w0 * v0.w;
        a1.x = a1.x * c1 + w1 * v1.x;  a1.y = a1.y * c1 + w1 * v1.y;
        a1.z = a1.z * c1 + w1 * v1.z;  a1.w = a1.w * c1 + w1 * v1.w;
    }

    float i0 = 1.f / d0;
    float i1 = 1.f / d1;
    out4[n * 64 + lane]      = make_float4(a0.x * i0, a0.y * i0, a0.z * i0, a0.w * i0);
    out4[n * 64 + 32 + lane] = make_float4(a1.x * i1, a1.y * i1, a1.z * i1, a1.w * i1);
}

// ---------------- launch ----------------
extern "C" void kernel_launch(void* const* d_in, const int* in_sizes, int n_in,
                              void* d_out, int out_size) {
    const float* x  = (const float*)d_in[0];
    const int*   ei = (const int*)d_in[1];     // int32: JAX x64-disabled
    const float* W  = (const float*)d_in[2];
    const float* b  = (const float*)d_in[3];
    const float* a  = (const float*)d_in[4];
    float*       out = (float*)d_out;

    dim3 gg((NN + 63) / 64, 2);
    k_gemm<<<gg, 256>>>(x, W, b, a);

    k_zero<<<(NN + 255) / 256, 256>>>();
    k_count<<<(NE + 255) / 256, 256>>>(ei);
    k_scan<<<1, 1024>>>();
    k_scatter<<<(NE + 255) / 256, 256>>>(ei);

    k_agg<<<(NN * 32 + 255) / 256, 256>>>(out);
}

// round 3
// speedup vs baseline: 1.5145x; 1.5145x over previous
#include <cuda_runtime.h>
#include <math.h>

#define NN 50000
#define NE 800000
#define IND 256
#define DOUT 128
#define FDIM 256   // 2 heads * 128

// ---------------- scratch (static __device__, no allocation) ----------------
__device__ float g_Wh[NN * FDIM];   // 51.2 MB - fits L2
__device__ float g_s[NN * 2];
__device__ float g_t[NN * 2];
__device__ int   g_deg[NN];
__device__ int   g_off[NN + 1];
__device__ int   g_cur[NN];
__device__ int   g_dst[NE];

// ---------------- CSR build ----------------
__global__ void k_zero() {
    int i = blockIdx.x * blockDim.x + threadIdx.x;
    if (i < NN) g_deg[i] = 0;
}

// edge_index is int32 (JAX default x64-disabled downcasts int64 -> int32)
__global__ void k_count(const int* __restrict__ ei) {
    int e = blockIdx.x * blockDim.x + threadIdx.x;
    if (e < NE) {
        unsigned s = (unsigned)ei[e];
        if (s < NN) atomicAdd(&g_deg[s], 1);
    }
}

// single-block scan: 1024 threads x 49-element chunks, 2-level shuffle scan
__global__ __launch_bounds__(1024) void k_scan() {
    const int CH = 49;                      // 1024*49 = 50176 >= NN
    int tid  = threadIdx.x;
    int lane = tid & 31;
    int wid  = tid >> 5;
    int beg  = tid * CH;
    int end  = beg + CH; if (end > NN) end = NN;

    int sum = 0;
    for (int i = beg; i < end; i++) sum += g_deg[i];

    // inclusive warp scan of thread sums
    int v = sum;
#pragma unroll
    for (int o = 1; o < 32; o <<= 1) {
        int u = __shfl_up_sync(0xffffffffu, v, o);
        if (lane >= o) v += u;
    }
    __shared__ int wsum[32];
    if (lane == 31) wsum[wid] = v;
    __syncthreads();
    if (wid == 0) {
        int w = wsum[lane];
#pragma unroll
        for (int o = 1; o < 32; o <<= 1) {
            int u = __shfl_up_sync(0xffffffffu, w, o);
            if (lane >= o) w += u;
        }
        wsum[lane] = w;
    }
    __syncthreads();

    int base = v - sum + ((wid > 0) ? wsum[wid - 1] : 0);  // exclusive prefix
    int run = base;
    for (int i = beg; i < end; i++) {
        g_off[i] = run;
        g_cur[i] = run;
        run += g_deg[i];
    }
    if (tid == 1023) g_off[NN] = run;   // beg > NN for tid 1023 -> run == total
}

__global__ void k_scatter(const int* __restrict__ ei) {
    int e = blockIdx.x * blockDim.x + threadIdx.x;
    if (e < NE) {
        unsigned s = (unsigned)ei[e];
        unsigned d = (unsigned)ei[NE + e];
        if (s < NN && d < NN) {
            int p = atomicAdd(&g_cur[s], 1);
            if (p >= 0 && p < NE) g_dst[p] = (int)d;
        }
    }
}

// ---------------- GEMM: Wh = x @ W + b, fused s/t epilogue ----------------
// BM=64, BN=128 (one head per blockIdx.y), BK=32, 256 threads, f32x2 packed FMA.
__global__ __launch_bounds__(256) void k_gemm(const float* __restrict__ x,
                                              const float* __restrict__ W,
                                              const float* __restrict__ b,
                                              const float* __restrict__ a) {
    __shared__ float xs[32][65];   // xs[k][row], padded
    __shared__ float ws[32][128];  // ws[k][n]

    int tid  = threadIdx.x;
    int h    = blockIdx.y;                 // head / 128-col tile
    int row0 = blockIdx.x * 64;
    int tr   = tid >> 5;                   // warp id: rows tr*8 .. tr*8+7
    int tc   = tid & 31;                   // cols tc*4 .. tc*4+3 (within head)

    unsigned long long acc2[8][2];
    unsigned long long zz;
    asm("mov.b64 %0, {%1, %1};" : "=l"(zz) : "r"(0u));
#pragma unroll
    for (int i = 0; i < 8; i++) { acc2[i][0] = zz; acc2[i][1] = zz; }

    for (int k0 = 0; k0 < IND; k0 += 32) {
        // load x tile (64 rows x 32 k), transposed into xs[k][row]
#pragma unroll
        for (int q = 0; q < 2; q++) {
            int idx  = tid * 2 + q;
            int r    = idx >> 3;
            int kq   = (idx & 7) << 2;
            int grow = row0 + r;
            float4 xv = make_float4(0.f, 0.f, 0.f, 0.f);
            if (grow < NN) xv = *(const float4*)&x[grow * IND + k0 + kq];
            xs[kq + 0][r] = xv.x;
            xs[kq + 1][r] = xv.y;
            xs[kq + 2][r] = xv.z;
            xs[kq + 3][r] = xv.w;
        }
        // load W tile (32 k x 128 n)
        {
            int kr = tid >> 5;
            int nq = (tid & 31) << 2;
#pragma unroll
            for (int p = 0; p < 4; p++) {
                int k = kr + p * 8;
                *(float4*)&ws[k][nq] = *(const float4*)&W[(k0 + k) * FDIM + h * 128 + nq];
            }
        }
        __syncthreads();
#pragma unroll
        for (int kk = 0; kk < 32; kk++) {
            unsigned long long rn01 = *(const unsigned long long*)&ws[kk][tc * 4];
            unsigned long long rn23 = *(const unsigned long long*)&ws[kk][tc * 4 + 2];
#pragma unroll
            for (int i = 0; i < 8; i++) {
                float rm = xs[kk][tr * 8 + i];
                unsigned long long am;
                asm("mov.b64 %0, {%1, %1};" : "=l"(am) : "r"(__float_as_uint(rm)));
                asm("fma.rn.f32x2 %0, %1, %2, %3;"
                    : "=l"(acc2[i][0]) : "l"(am), "l"(rn01), "l"(acc2[i][0]));
                asm("fma.rn.f32x2 %0, %1, %2, %3;"
                    : "=l"(acc2[i][1]) : "l"(am), "l"(rn23), "l"(acc2[i][1]));
            }
        }
        __syncthreads();
    }

    // epilogue: bias, store Wh, fused s/t dot + warp reduce
    float4 bb = *(const float4*)&b[h * 128 + tc * 4];
    float as0 = a[tc * 4 + 0], as1 = a[tc * 4 + 1], as2 = a[tc * 4 + 2], as3 = a[tc * 4 + 3];
    float at0 = a[128 + tc * 4 + 0], at1 = a[128 + tc * 4 + 1];
    float at2 = a[128 + tc * 4 + 2], at3 = a[128 + tc * 4 + 3];

#pragma unroll
    for (int i = 0; i < 8; i++) {
        int grow = row0 + tr * 8 + i;
        unsigned int u0, u1, u2, u3;
        asm("mov.b64 {%0, %1}, %2;" : "=r"(u0), "=r"(u1) : "l"(acc2[i][0]));
        asm("mov.b64 {%0, %1}, %2;" : "=r"(u2), "=r"(u3) : "l"(acc2[i][1]));
        float f0 = __uint_as_float(u0) + bb.x;
        float f1 = __uint_as_float(u1) + bb.y;
        float f2 = __uint_as_float(u2) + bb.z;
        float f3 = __uint_as_float(u3) + bb.w;
        float ps = f0 * as0 + f1 * as1 + f2 * as2 + f3 * as3;
        float pt = f0 * at0 + f1 * at1 + f2 * at2 + f3 * at3;
#pragma unroll
        for (int off = 16; off > 0; off >>= 1) {
            ps += __shfl_down_sync(0xffffffffu, ps, off);
            pt += __shfl_down_sync(0xffffffffu, pt, off);
        }
        if (grow < NN) {
            *(float4*)&g_Wh[grow * FDIM + h * 128 + tc * 4] = make_float4(f0, f1, f2, f3);
            if (tc == 0) {
                g_s[grow * 2 + h] = ps;
                g_t[grow * 2 + h] = pt;
            }
        }
    }
}

// ---------------- per-node online softmax + aggregation (1 warp / node) ----
__global__ __launch_bounds__(256) void k_agg(float* __restrict__ out) {
    int gwarp = (blockIdx.x * blockDim.x + threadIdx.x) >> 5;
    int lane  = threadIdx.x & 31;
    if (gwarp >= NN) return;
    int n = gwarp;
    int start = g_off[n];
    int end   = g_off[n + 1];

    const float4* wh4  = (const float4*)g_Wh;
    float4*       out4 = (float4*)out;

    if (end == start) {  // deg == 0 -> h' = Wh
        out4[n * 64 + lane]      = wh4[n * 64 + lane];
        out4[n * 64 + 32 + lane] = wh4[n * 64 + 32 + lane];
        return;
    }

    float2 ss = *(const float2*)&g_s[n * 2];
    float m0 = -INFINITY, m1 = -INFINITY;
    float d0 = 0.f, d1 = 0.f;
    float4 a0 = make_float4(0.f, 0.f, 0.f, 0.f);
    float4 a1 = make_float4(0.f, 0.f, 0.f, 0.f);

    int dnext = g_dst[start];
    for (int i = start; i < end; i++) {
        int dd = dnext;
        if (i + 1 < end) dnext = g_dst[i + 1];

        float2 tt = *(const float2*)&g_t[dd * 2];
        float e0 = ss.x + tt.x; e0 = (e0 > 0.f) ? e0 : 0.2f * e0;
        float e1 = ss.y + tt.y; e1 = (e1 > 0.f) ? e1 : 0.2f * e1;

        float nm0 = fmaxf(m0, e0), nm1 = fmaxf(m1, e1);
        float c0 = __expf(m0 - nm0), c1 = __expf(m1 - nm1);
        float w0 = __expf(e0 - nm0), w1 = __expf(e1 - nm1);
        d0 = d0 * c0 + w0;  m0 = nm0;
        d1 = d1 * c1 + w1;  m1 = nm1;

        float4 v0 = wh4[dd * 64 + lane];
        float4 v1 = wh4[dd * 64 + 32 + lane];
        a0.x = a0.x * c0 + w0 * v0.x;  a0.y = a0.y * c0 + w0 * v0.y;
        a0.z = a0.z * c0 + w0 * v0.z;  a0.w = a0.w * c0 + w0 * v0.w;
        a1.x = a1.x * c1 + w1 * v1.x;  a1.y = a1.y * c1 + w1 * v1.y;
        a1.z = a1.z * c1 + w1 * v1.z;  a1.w = a1.w * c1 + w1 * v1.w;
    }

    float i0 = 1.f / d0;
    float i1 = 1.f / d1;
    out4[n * 64 + lane]      = make_float4(a0.x * i0, a0.y * i0, a0.z * i0, a0.w * i0);
    out4[n * 64 + 32 + lane] = make_float4(a1.x * i1, a1.y * i1, a1.z * i1, a1.w * i1);
}

// ---------------- launch ----------------
extern "C" void kernel_launch(void* const* d_in, const int* in_sizes, int n_in,
                              void* d_out, int out_size) {
    const float* x  = (const float*)d_in[0];
    const int*   ei = (const int*)d_in[1];     // int32: JAX x64-disabled
    const float* W  = (const float*)d_in[2];
    const float* b  = (const float*)d_in[3];
    const float* a  = (const float*)d_in[4];
    float*       out = (float*)d_out;

    dim3 gg((NN + 63) / 64, 2);
    k_gemm<<<gg, 256>>>(x, W, b, a);

    k_zero<<<(NN + 255) / 256, 256>>>();
    k_count<<<(NE + 255) / 256, 256>>>(ei);
    k_scan<<<1, 1024>>>();
    k_scatter<<<(NE + 255) / 256, 256>>>(ei);

    k_agg<<<(NN * 32 + 255) / 256, 256>>>(out);
}

// round 4
// speedup vs baseline: 1.9506x; 1.2880x over previous
#include <cuda_runtime.h>
#include <math.h>

#define NN 50000
#define NE 800000
#define IND 256
#define DOUT 128
#define FDIM 256   // 2 heads * 128
#define SCAN_BLKS 49   // ceil(NN / 1024)

// ---------------- scratch (static __device__, no allocation) ----------------
__device__ float g_Wh[NN * FDIM];   // 51.2 MB - fits L2
__device__ float g_s[NN * 2];
__device__ float g_t[NN * 2];
__device__ __align__(16) int g_deg[NN];
__device__ __align__(16) int g_off[NN + 4];
__device__ __align__(16) int g_cur[NN];
__device__ int g_dst[NE];
__device__ int g_bsum[64];
__device__ int g_bpre[64];

// ---------------- CSR build ----------------
__global__ void k_zero() {
    int i = blockIdx.x * blockDim.x + threadIdx.x;
    if (i < NN) g_deg[i] = 0;
}

// edge_index is int32 (JAX default x64-disabled downcasts int64 -> int32)
__global__ void k_count(const int* __restrict__ ei) {
    int e = blockIdx.x * blockDim.x + threadIdx.x;
    if (e < NE) {
        unsigned s = (unsigned)ei[e];
        if (s < NN) atomicAdd(&g_deg[s], 1);
    }
}

// phase 1: block-local exclusive scan (49 blocks x 256 thr x 4 nodes)
__global__ __launch_bounds__(256) void k_scan1() {
    int b = blockIdx.x, t = threadIdx.x;
    int lane = t & 31, wid = t >> 5;
    int base = b * 1024 + t * 4;

    int v0 = 0, v1 = 0, v2 = 0, v3 = 0;
    if (base + 3 < NN) {
        int4 q = *(const int4*)&g_deg[base];
        v0 = q.x; v1 = q.y; v2 = q.z; v3 = q.w;
    }
    int s = v0 + v1 + v2 + v3;

    int inc = s;
#pragma unroll
    for (int o = 1; o < 32; o <<= 1) {
        int u = __shfl_up_sync(0xffffffffu, inc, o);
        if (lane >= o) inc += u;
    }
    __shared__ int ws[8];
    if (lane == 31) ws[wid] = inc;
    __syncthreads();
    int wpre = 0;
#pragma unroll
    for (int w = 0; w < 8; w++) wpre += (w < wid) ? ws[w] : 0;

    int ex = wpre + inc - s;   // exclusive prefix within block
    if (base + 3 < NN) {
        int4 o;
        o.x = ex;
        o.y = ex + v0;
        o.z = ex + v0 + v1;
        o.w = ex + v0 + v1 + v2;
        *(int4*)&g_off[base] = o;
    }
    if (t == 255) g_bsum[b] = ex + s;   // block total
}

// phase 2: scan the 49 block sums (1 block, 64 thr)
__global__ void k_scan2() {
    int t = threadIdx.x;
    int lane = t & 31, wid = t >> 5;
    int v = (t < SCAN_BLKS) ? g_bsum[t] : 0;
    int inc = v;
#pragma unroll
    for (int o = 1; o < 32; o <<= 1) {
        int u = __shfl_up_sync(0xffffffffu, inc, o);
        if (lane >= o) inc += u;
    }
    __shared__ int w0tot;
    if (wid == 0 && lane == 31) w0tot = inc;
    __syncthreads();
    int ex = inc - v + (wid ? w0tot : 0);
    if (t < SCAN_BLKS) g_bpre[t] = ex;
    if (t == SCAN_BLKS - 1) g_off[NN] = ex + v;   // grand total
}

// phase 3: add block prefix, materialize g_off/g_cur
__global__ __launch_bounds__(256) void k_scan3() {
    int b = blockIdx.x, t = threadIdx.x;
    int base = b * 1024 + t * 4;
    int p = g_bpre[b];
    if (base + 3 < NN) {
        int4 o = *(const int4*)&g_off[base];
        o.x += p; o.y += p; o.z += p; o.w += p;
        *(int4*)&g_off[base] = o;
        *(int4*)&g_cur[base] = o;
    }
}

__global__ void k_scatter(const int* __restrict__ ei) {
    int e = blockIdx.x * blockDim.x + threadIdx.x;
    if (e < NE) {
        unsigned s = (unsigned)ei[e];
        unsigned d = (unsigned)ei[NE + e];
        if (s < NN && d < NN) {
            int p = atomicAdd(&g_cur[s], 1);
            if (p >= 0 && p < NE) g_dst[p] = (int)d;
        }
    }
}

// ---------------- GEMM: Wh = x @ W + b, fused s/t epilogue ----------------
// BM=64, BN=128 (one head per blockIdx.y), BK=32, 256 threads, f32x2 packed FMA.
__global__ __launch_bounds__(256) void k_gemm(const float* __restrict__ x,
                                              const float* __restrict__ W,
                                              const float* __restrict__ b,
                                              const float* __restrict__ a) {
    __shared__ float xs[32][65];   // xs[k][row], padded
    __shared__ float ws[32][128];  // ws[k][n]

    int tid  = threadIdx.x;
    int h    = blockIdx.y;                 // head / 128-col tile
    int row0 = blockIdx.x * 64;
    int tr   = tid >> 5;                   // warp id: rows tr*8 .. tr*8+7
    int tc   = tid & 31;                   // cols tc*4 .. tc*4+3 (within head)

    unsigned long long acc2[8][2];
    unsigned long long zz;
    asm("mov.b64 %0, {%1, %1};" : "=l"(zz) : "r"(0u));
#pragma unroll
    for (int i = 0; i < 8; i++) { acc2[i][0] = zz; acc2[i][1] = zz; }

    for (int k0 = 0; k0 < IND; k0 += 32) {
        // load x tile (64 rows x 32 k), transposed into xs[k][row]
#pragma unroll
        for (int q = 0; q < 2; q++) {
            int idx  = tid * 2 + q;
            int r    = idx >> 3;
            int kq   = (idx & 7) << 2;
            int grow = row0 + r;
            float4 xv = make_float4(0.f, 0.f, 0.f, 0.f);
            if (grow < NN) xv = *(const float4*)&x[grow * IND + k0 + kq];
            xs[kq + 0][r] = xv.x;
            xs[kq + 1][r] = xv.y;
            xs[kq + 2][r] = xv.z;
            xs[kq + 3][r] = xv.w;
        }
        // load W tile (32 k x 128 n)
        {
            int kr = tid >> 5;
            int nq = (tid & 31) << 2;
#pragma unroll
            for (int p = 0; p < 4; p++) {
                int k = kr + p * 8;
                *(float4*)&ws[k][nq] = *(const float4*)&W[(k0 + k) * FDIM + h * 128 + nq];
            }
        }
        __syncthreads();
#pragma unroll
        for (int kk = 0; kk < 32; kk++) {
            unsigned long long rn01 = *(const unsigned long long*)&ws[kk][tc * 4];
            unsigned long long rn23 = *(const unsigned long long*)&ws[kk][tc * 4 + 2];
#pragma unroll
            for (int i = 0; i < 8; i++) {
                float rm = xs[kk][tr * 8 + i];
                unsigned long long am;
                asm("mov.b64 %0, {%1, %1};" : "=l"(am) : "r"(__float_as_uint(rm)));
                asm("fma.rn.f32x2 %0, %1, %2, %3;"
                    : "=l"(acc2[i][0]) : "l"(am), "l"(rn01), "l"(acc2[i][0]));
                asm("fma.rn.f32x2 %0, %1, %2, %3;"
                    : "=l"(acc2[i][1]) : "l"(am), "l"(rn23), "l"(acc2[i][1]));
            }
        }
        __syncthreads();
    }

    // epilogue: bias, store Wh, fused s/t dot + warp reduce
    float4 bb = *(const float4*)&b[h * 128 + tc * 4];
    float as0 = a[tc * 4 + 0], as1 = a[tc * 4 + 1], as2 = a[tc * 4 + 2], as3 = a[tc * 4 + 3];
    float at0 = a[128 + tc * 4 + 0], at1 = a[128 + tc * 4 + 1];
    float at2 = a[128 + tc * 4 + 2], at3 = a[128 + tc * 4 + 3];

#pragma unroll
    for (int i = 0; i < 8; i++) {
        int grow = row0 + tr * 8 + i;
        unsigned int u0, u1, u2, u3;
        asm("mov.b64 {%0, %1}, %2;" : "=r"(u0), "=r"(u1) : "l"(acc2[i][0]));
        asm("mov.b64 {%0, %1}, %2;" : "=r"(u2), "=r"(u3) : "l"(acc2[i][1]));
        float f0 = __uint_as_float(u0) + bb.x;
        float f1 = __uint_as_float(u1) + bb.y;
        float f2 = __uint_as_float(u2) + bb.z;
        float f3 = __uint_as_float(u3) + bb.w;
        float ps = f0 * as0 + f1 * as1 + f2 * as2 + f3 * as3;
        float pt = f0 * at0 + f1 * at1 + f2 * at2 + f3 * at3;
#pragma unroll
        for (int off = 16; off > 0; off >>= 1) {
            ps += __shfl_down_sync(0xffffffffu, ps, off);
            pt += __shfl_down_sync(0xffffffffu, pt, off);
        }
        if (grow < NN) {
            *(float4*)&g_Wh[grow * FDIM + h * 128 + tc * 4] = make_float4(f0, f1, f2, f3);
            if (tc == 0) {
                g_s[grow * 2 + h] = ps;
                g_t[grow * 2 + h] = pt;
            }
        }
    }
}

// ---------------- per-node online softmax + aggregation (1 warp / node) ----
__global__ __launch_bounds__(256) void k_agg(float* __restrict__ out) {
    int gwarp = (blockIdx.x * blockDim.x + threadIdx.x) >> 5;
    int lane  = threadIdx.x & 31;
    if (gwarp >= NN) return;
    int n = gwarp;
    int start = g_off[n];
    int end   = g_off[n + 1];

    const float4* wh4  = (const float4*)g_Wh;
    float4*       out4 = (float4*)out;

    if (end == start) {  // deg == 0 -> h' = Wh
        out4[n * 64 + lane]      = wh4[n * 64 + lane];
        out4[n * 64 + 32 + lane] = wh4[n * 64 + 32 + lane];
        return;
    }

    float2 ss = *(const float2*)&g_s[n * 2];
    float m0 = -INFINITY, m1 = -INFINITY;
    float d0 = 0.f, d1 = 0.f;
    float4 a0 = make_float4(0.f, 0.f, 0.f, 0.f);
    float4 a1 = make_float4(0.f, 0.f, 0.f, 0.f);

    int dnext = g_dst[start];
    for (int i = start; i < end; i++) {
        int dd = dnext;
        if (i + 1 < end) dnext = g_dst[i + 1];

        float2 tt = *(const float2*)&g_t[dd * 2];
        float e0 = ss.x + tt.x; e0 = (e0 > 0.f) ? e0 : 0.2f * e0;
        float e1 = ss.y + tt.y; e1 = (e1 > 0.f) ? e1 : 0.2f * e1;

        float nm0 = fmaxf(m0, e0), nm1 = fmaxf(m1, e1);
        float c0 = __expf(m0 - nm0), c1 = __expf(m1 - nm1);
        float w0 = __expf(e0 - nm0), w1 = __expf(e1 - nm1);
        d0 = d0 * c0 + w0;  m0 = nm0;
        d1 = d1 * c1 + w1;  m1 = nm1;

        float4 v0 = wh4[dd * 64 + lane];
        float4 v1 = wh4[dd * 64 + 32 + lane];
        a0.x = a0.x * c0 + w0 * v0.x;  a0.y = a0.y * c0 + w0 * v0.y;
        a0.z = a0.z * c0 + w0 * v0.z;  a0.w = a0.w * c0 + w0 * v0.w;
        a1.x = a1.x * c1 + w1 * v1.x;  a1.y = a1.y * c1 + w1 * v1.y;
        a1.z = a1.z * c1 + w1 * v1.z;  a1.w = a1.w * c1 + w1 * v1.w;
    }

    float i0 = 1.f / d0;
    float i1 = 1.f / d1;
    out4[n * 64 + lane]      = make_float4(a0.x * i0, a0.y * i0, a0.z * i0, a0.w * i0);
    out4[n * 64 + 32 + lane] = make_float4(a1.x * i1, a1.y * i1, a1.z * i1, a1.w * i1);
}

// ---------------- launch ----------------
extern "C" void kernel_launch(void* const* d_in, const int* in_sizes, int n_in,
                              void* d_out, int out_size) {
    const float* x  = (const float*)d_in[0];
    const int*   ei = (const int*)d_in[1];     // int32: JAX x64-disabled
    const float* W  = (const float*)d_in[2];
    const float* b  = (const float*)d_in[3];
    const float* a  = (const float*)d_in[4];
    float*       out = (float*)d_out;

    dim3 gg((NN + 63) / 64, 2);
    k_gemm<<<gg, 256>>>(x, W, b, a);

    k_zero<<<(NN + 255) / 256, 256>>>();
    k_count<<<(NE + 255) / 256, 256>>>(ei);
    k_scan1<<<SCAN_BLKS, 256>>>();
    k_scan2<<<1, 64>>>();
    k_scan3<<<SCAN_BLKS, 256>>>();
    k_scatter<<<(NE + 255) / 256, 256>>>(ei);

    k_agg<<<(NN * 32 + 255) / 256, 256>>>(out);
}

// round 5
// speedup vs baseline: 2.0396x; 1.0456x over previous
#include <cuda_runtime.h>
#include <math.h>

#define NN 50000
#define NE 800000
#define IND 256
#define DOUT 128
#define FDIM 256   // 2 heads * 128
#define SCAN_BLKS 49   // ceil(NN / 1024)

// ---------------- scratch (static __device__, no allocation) ----------------
__device__ float g_Wh[NN * FDIM];   // 51.2 MB - fits L2
__device__ float g_s[NN * 2];
__device__ float g_t[NN * 2];
__device__ __align__(16) int g_deg[NN];
__device__ __align__(16) int g_off[NN + 4];
__device__ __align__(16) int g_cur[NN];
__device__ int g_dst[NE];
__device__ int g_bsum[64];
__device__ int g_bpre[64];

// ---------------- CSR build ----------------
__global__ void k_zero() {
    int i = blockIdx.x * blockDim.x + threadIdx.x;
    if (i < NN) g_deg[i] = 0;
}

// edge_index is int32 (JAX default x64-disabled downcasts int64 -> int32)
__global__ void k_count(const int* __restrict__ ei) {
    int e = blockIdx.x * blockDim.x + threadIdx.x;
    if (e < NE) {
        unsigned s = (unsigned)ei[e];
        if (s < NN) atomicAdd(&g_deg[s], 1);
    }
}

// phase 1: block-local exclusive scan (49 blocks x 256 thr x 4 nodes)
__global__ __launch_bounds__(256) void k_scan1() {
    int b = blockIdx.x, t = threadIdx.x;
    int lane = t & 31, wid = t >> 5;
    int base = b * 1024 + t * 4;

    int v0 = 0, v1 = 0, v2 = 0, v3 = 0;
    if (base + 3 < NN) {
        int4 q = *(const int4*)&g_deg[base];
        v0 = q.x; v1 = q.y; v2 = q.z; v3 = q.w;
    }
    int s = v0 + v1 + v2 + v3;

    int inc = s;
#pragma unroll
    for (int o = 1; o < 32; o <<= 1) {
        int u = __shfl_up_sync(0xffffffffu, inc, o);
        if (lane >= o) inc += u;
    }
    __shared__ int ws[8];
    if (lane == 31) ws[wid] = inc;
    __syncthreads();
    int wpre = 0;
#pragma unroll
    for (int w = 0; w < 8; w++) wpre += (w < wid) ? ws[w] : 0;

    int ex = wpre + inc - s;   // exclusive prefix within block
    if (base + 3 < NN) {
        int4 o;
        o.x = ex;
        o.y = ex + v0;
        o.z = ex + v0 + v1;
        o.w = ex + v0 + v1 + v2;
        *(int4*)&g_off[base] = o;
    }
    if (t == 255) g_bsum[b] = ex + s;   // block total
}

// phase 2: scan the 49 block sums (1 block, 64 thr)
__global__ void k_scan2() {
    int t = threadIdx.x;
    int lane = t & 31, wid = t >> 5;
    int v = (t < SCAN_BLKS) ? g_bsum[t] : 0;
    int inc = v;
#pragma unroll
    for (int o = 1; o < 32; o <<= 1) {
        int u = __shfl_up_sync(0xffffffffu, inc, o);
        if (lane >= o) inc += u;
    }
    __shared__ int w0tot;
    if (wid == 0 && lane == 31) w0tot = inc;
    __syncthreads();
    int ex = inc - v + (wid ? w0tot : 0);
    if (t < SCAN_BLKS) g_bpre[t] = ex;
    if (t == SCAN_BLKS - 1) g_off[NN] = ex + v;   // grand total
}

// phase 3: add block prefix, materialize g_off/g_cur
__global__ __launch_bounds__(256) void k_scan3() {
    int b = blockIdx.x, t = threadIdx.x;
    int base = b * 1024 + t * 4;
    int p = g_bpre[b];
    if (base + 3 < NN) {
        int4 o = *(const int4*)&g_off[base];
        o.x += p; o.y += p; o.z += p; o.w += p;
        *(int4*)&g_off[base] = o;
        *(int4*)&g_cur[base] = o;
    }
}

__global__ void k_scatter(const int* __restrict__ ei) {
    int e = blockIdx.x * blockDim.x + threadIdx.x;
    if (e < NE) {
        unsigned s = (unsigned)ei[e];
        unsigned d = (unsigned)ei[NE + e];
        if (s < NN && d < NN) {
            int p = atomicAdd(&g_cur[s], 1);
            if (p >= 0 && p < NE) g_dst[p] = (int)d;
        }
    }
}

// ---------------- GEMM: Wh = x @ W + b, fused s/t epilogue ----------------
// BM=64, BN=128 (one head per blockIdx.y), BK=32, 256 threads, f32x2 packed FMA.
__global__ __launch_bounds__(256) void k_gemm(const float* __restrict__ x,
                                              const float* __restrict__ W,
                                              const float* __restrict__ b,
                                              const float* __restrict__ a) {
    __shared__ float xs[32][65];   // xs[k][row], padded
    __shared__ float ws[32][128];  // ws[k][n]

    int tid  = threadIdx.x;
    int h    = blockIdx.y;                 // head / 128-col tile
    int row0 = blockIdx.x * 64;
    int tr   = tid >> 5;                   // warp id: rows tr*8 .. tr*8+7
    int tc   = tid & 31;                   // cols tc*4 .. tc*4+3 (within head)

    unsigned long long acc2[8][2];
    unsigned long long zz;
    asm("mov.b64 %0, {%1, %1};" : "=l"(zz) : "r"(0u));
#pragma unroll
    for (int i = 0; i < 8; i++) { acc2[i][0] = zz; acc2[i][1] = zz; }

    for (int k0 = 0; k0 < IND; k0 += 32) {
        // load x tile (64 rows x 32 k), transposed into xs[k][row]
#pragma unroll
        for (int q = 0; q < 2; q++) {
            int idx  = tid * 2 + q;
            int r    = idx >> 3;
            int kq   = (idx & 7) << 2;
            int grow = row0 + r;
            float4 xv = make_float4(0.f, 0.f, 0.f, 0.f);
            if (grow < NN) xv = *(const float4*)&x[grow * IND + k0 + kq];
            xs[kq + 0][r] = xv.x;
            xs[kq + 1][r] = xv.y;
            xs[kq + 2][r] = xv.z;
            xs[kq + 3][r] = xv.w;
        }
        // load W tile (32 k x 128 n)
        {
            int kr = tid >> 5;
            int nq = (tid & 31) << 2;
#pragma unroll
            for (int p = 0; p < 4; p++) {
                int k = kr + p * 8;
                *(float4*)&ws[k][nq] = *(const float4*)&W[(k0 + k) * FDIM + h * 128 + nq];
            }
        }
        __syncthreads();
#pragma unroll
        for (int kk = 0; kk < 32; kk++) {
            unsigned long long rn01 = *(const unsigned long long*)&ws[kk][tc * 4];
            unsigned long long rn23 = *(const unsigned long long*)&ws[kk][tc * 4 + 2];
#pragma unroll
            for (int i = 0; i < 8; i++) {
                float rm = xs[kk][tr * 8 + i];
                unsigned long long am;
                asm("mov.b64 %0, {%1, %1};" : "=l"(am) : "r"(__float_as_uint(rm)));
                asm("fma.rn.f32x2 %0, %1, %2, %3;"
                    : "=l"(acc2[i][0]) : "l"(am), "l"(rn01), "l"(acc2[i][0]));
                asm("fma.rn.f32x2 %0, %1, %2, %3;"
                    : "=l"(acc2[i][1]) : "l"(am), "l"(rn23), "l"(acc2[i][1]));
            }
        }
        __syncthreads();
    }

    // epilogue: bias, store Wh, fused s/t dot + warp reduce
    float4 bb = *(const float4*)&b[h * 128 + tc * 4];
    float as0 = a[tc * 4 + 0], as1 = a[tc * 4 + 1], as2 = a[tc * 4 + 2], as3 = a[tc * 4 + 3];
    float at0 = a[128 + tc * 4 + 0], at1 = a[128 + tc * 4 + 1];
    float at2 = a[128 + tc * 4 + 2], at3 = a[128 + tc * 4 + 3];

#pragma unroll
    for (int i = 0; i < 8; i++) {
        int grow = row0 + tr * 8 + i;
        unsigned int u0, u1, u2, u3;
        asm("mov.b64 {%0, %1}, %2;" : "=r"(u0), "=r"(u1) : "l"(acc2[i][0]));
        asm("mov.b64 {%0, %1}, %2;" : "=r"(u2), "=r"(u3) : "l"(acc2[i][1]));
        float f0 = __uint_as_float(u0) + bb.x;
        float f1 = __uint_as_float(u1) + bb.y;
        float f2 = __uint_as_float(u2) + bb.z;
        float f3 = __uint_as_float(u3) + bb.w;
        float ps = f0 * as0 + f1 * as1 + f2 * as2 + f3 * as3;
        float pt = f0 * at0 + f1 * at1 + f2 * at2 + f3 * at3;
#pragma unroll
        for (int off = 16; off > 0; off >>= 1) {
            ps += __shfl_down_sync(0xffffffffu, ps, off);
            pt += __shfl_down_sync(0xffffffffu, pt, off);
        }
        if (grow < NN) {
            *(float4*)&g_Wh[grow * FDIM + h * 128 + tc * 4] = make_float4(f0, f1, f2, f3);
            if (tc == 0) {
                g_s[grow * 2 + h] = ps;
                g_t[grow * 2 + h] = pt;
            }
        }
    }
}

// ---------------- per-node online softmax + aggregation (1 warp / node) ----
__global__ __launch_bounds__(512) void k_agg(float* __restrict__ out) {
    int gwarp = (blockIdx.x * blockDim.x + threadIdx.x) >> 5;
    int lane  = threadIdx.x & 31;
    if (gwarp >= NN) return;
    int n = gwarp;
    int start = g_off[n];
    int end   = g_off[n + 1];

    const float4* wh4  = (const float4*)g_Wh;
    float4*       out4 = (float4*)out;

    if (end == start) {  // deg == 0 -> h' = Wh
        out4[n * 64 + lane]      = wh4[n * 64 + lane];
        out4[n * 64 + 32 + lane] = wh4[n * 64 + 32 + lane];
        return;
    }

    float2 ss = *(const float2*)&g_s[n * 2];
    float m0 = -INFINITY, m1 = -INFINITY;
    float d0 = 0.f, d1 = 0.f;
    float4 a0 = make_float4(0.f, 0.f, 0.f, 0.f);
    float4 a1 = make_float4(0.f, 0.f, 0.f, 0.f);

    int dnext = g_dst[start];
    for (int i = start; i < end; i++) {
        int dd = dnext;
        if (i + 1 < end) dnext = g_dst[i + 1];

        float2 tt = *(const float2*)&g_t[dd * 2];
        float e0 = ss.x + tt.x; e0 = (e0 > 0.f) ? e0 : 0.2f * e0;
        float e1 = ss.y + tt.y; e1 = (e1 > 0.f) ? e1 : 0.2f * e1;

        float nm0 = fmaxf(m0, e0), nm1 = fmaxf(m1, e1);
        float c0 = __expf(m0 - nm0), c1 = __expf(m1 - nm1);
        float w0 = __expf(e0 - nm0), w1 = __expf(e1 - nm1);
        d0 = d0 * c0 + w0;  m0 = nm0;
        d1 = d1 * c1 + w1;  m1 = nm1;

        float4 v0 = wh4[dd * 64 + lane];
        float4 v1 = wh4[dd * 64 + 32 + lane];
        a0.x = a0.x * c0 + w0 * v0.x;  a0.y = a0.y * c0 + w0 * v0.y;
        a0.z = a0.z * c0 + w0 * v0.z;  a0.w = a0.w * c0 + w0 * v0.w;
        a1.x = a1.x * c1 + w1 * v1.x;  a1.y = a1.y * c1 + w1 * v1.y;
        a1.z = a1.z * c1 + w1 * v1.z;  a1.w = a1.w * c1 + w1 * v1.w;
    }

    float i0 = 1.f / d0;
    float i1 = 1.f / d1;
    out4[n * 64 + lane]      = make_float4(a0.x * i0, a0.y * i0, a0.z * i0, a0.w * i0);
    out4[n * 64 + 32 + lane] = make_float4(a1.x * i1, a1.y * i1, a1.z * i1, a1.w * i1);
}

// ---------------- launch (fork-join: CSR build overlaps GEMM) --------------
static cudaStream_t g_s1 = 0;
static cudaEvent_t  g_evFork = 0, g_evJoin = 0;

extern "C" void kernel_launch(void* const* d_in, const int* in_sizes, int n_in,
                              void* d_out, int out_size) {
    const float* x  = (const float*)d_in[0];
    const int*   ei = (const int*)d_in[1];     // int32: JAX x64-disabled
    const float* W  = (const float*)d_in[2];
    const float* b  = (const float*)d_in[3];
    const float* a  = (const float*)d_in[4];
    float*       out = (float*)d_out;

    if (g_s1 == 0) {   // one-time resource creation (first call is eager, pre-capture)
        cudaStreamCreateWithFlags(&g_s1, cudaStreamNonBlocking);
        cudaEventCreateWithFlags(&g_evFork, cudaEventDisableTiming);
        cudaEventCreateWithFlags(&g_evJoin, cudaEventDisableTiming);
    }

    // fork: CSR chain on s1, independent of GEMM
    cudaEventRecord(g_evFork, 0);
    cudaStreamWaitEvent(g_s1, g_evFork, 0);

    k_zero<<<(NN + 255) / 256, 256, 0, g_s1>>>();
    k_count<<<(NE + 255) / 256, 256, 0, g_s1>>>(ei);
    k_scan1<<<SCAN_BLKS, 256, 0, g_s1>>>();
    k_scan2<<<1, 64, 0, g_s1>>>();
    k_scan3<<<SCAN_BLKS, 256, 0, g_s1>>>();
    k_scatter<<<(NE + 255) / 256, 256, 0, g_s1>>>(ei);
    cudaEventRecord(g_evJoin, g_s1);

    // GEMM on the main stream, concurrent with the CSR chain
    dim3 gg((NN + 63) / 64, 2);
    k_gemm<<<gg, 256>>>(x, W, b, a);

    // join, then aggregate
    cudaStreamWaitEvent(0, g_evJoin, 0);
    k_agg<<<(NN * 32 + 511) / 512, 512>>>(out);
}